// round 1
// baseline (speedup 1.0000x reference)
#include <cuda_runtime.h>
#include <math.h>

#define OUT_DIM 2048
#define IN_DIM  2048
#define RANK    4
#define NORM_EPS 1e-6f
#define MAG_EPS  1e-6f

// Scratch: materialized effective weight W[o][i] (row-major, K=IN contiguous)
__device__ float g_W[OUT_DIM * IN_DIM];
// stats: [0..3]=normA[r], [4..7]=normB[r], [8..11]=g[r]
__device__ float g_stats[3 * RANK];

// ---------------------------------------------------------------------------
// Kernel 1: per-rank column-norm of A, row-norm of B, softplus magnitude.
// One block, 128 threads: warp r handles rank r.
// ---------------------------------------------------------------------------
__global__ void stats_kernel(const float* __restrict__ A,
                             const float* __restrict__ Bm,
                             const float* __restrict__ mag) {
    int r    = threadIdx.x >> 5;
    int lane = threadIdx.x & 31;
    float sa = 0.f, sb = 0.f;
    for (int o = lane; o < OUT_DIM; o += 32) {
        float v = A[o * RANK + r];
        sa += v * v;
    }
    for (int i = lane; i < IN_DIM; i += 32) {
        float v = Bm[r * IN_DIM + i];
        sb += v * v;
    }
#pragma unroll
    for (int off = 16; off; off >>= 1) {
        sa += __shfl_xor_sync(0xffffffffu, sa, off);
        sb += __shfl_xor_sync(0xffffffffu, sb, off);
    }
    if (lane == 0) {
        g_stats[r]            = fmaxf(sqrtf(sa), NORM_EPS);
        g_stats[RANK + r]     = fmaxf(sqrtf(sb), NORM_EPS);
        float m  = mag[r];
        float sp = (m > 15.f) ? m : log1pf(expf(m));
        g_stats[2 * RANK + r] = sp + MAG_EPS;
    }
}

// ---------------------------------------------------------------------------
// Kernel 2: materialize W[o][i] = lut[idx[o][i]] * sum_r coef[o][r]*|B[r][i]|
// where coef[o][r] = |A[o][r]| / normA[r] * g[r] / normB[r].
// Each thread produces 4 consecutive i (float4/int4 vectorized).
// ---------------------------------------------------------------------------
__global__ void build_w_kernel(const float* __restrict__ A,
                               const float* __restrict__ Bm,
                               const int*   __restrict__ idx,
                               const float* __restrict__ lut) {
    int t = blockIdx.x * blockDim.x + threadIdx.x;   // over OUT*IN/4
    int per_row = IN_DIM / 4;
    int o  = t / per_row;
    int i4 = (t - o * per_row) * 4;

    float coef[RANK];
#pragma unroll
    for (int r = 0; r < RANK; r++) {
        coef[r] = fabsf(A[o * RANK + r]) * g_stats[2 * RANK + r]
                  / (g_stats[r] * g_stats[RANK + r]);
    }

    float s[4] = {0.f, 0.f, 0.f, 0.f};
#pragma unroll
    for (int r = 0; r < RANK; r++) {
        float4 bv = *(const float4*)(Bm + r * IN_DIM + i4);
        s[0] += coef[r] * fabsf(bv.x);
        s[1] += coef[r] * fabsf(bv.y);
        s[2] += coef[r] * fabsf(bv.z);
        s[3] += coef[r] * fabsf(bv.w);
    }

    int4 iv = *(const int4*)(idx + o * IN_DIM + i4);
    float4 w;
    w.x = lut[iv.x] * s[0];
    w.y = lut[iv.y] * s[1];
    w.z = lut[iv.z] * s[2];
    w.w = lut[iv.w] * s[3];
    *(float4*)(g_W + o * IN_DIM + i4) = w;
}

// ---------------------------------------------------------------------------
// Kernel 3: SGEMM  Y[m][n] = sum_k X[m][k] * W[n][k] + bias[n]
// 128x128 block tile, BK=8, 8x8 per thread, 256 threads.
// ---------------------------------------------------------------------------
#define BM 128
#define BN 128
#define BK 8
#define TM 8
#define TN 8

__global__ __launch_bounds__(256, 2)
void sgemm_kernel(const float* __restrict__ X,
                  const float* __restrict__ bias,
                  float* __restrict__ Y) {
    __shared__ float As[BK][BM];
    __shared__ float Bs[BK][BN];

    const int bm = blockIdx.y * BM;
    const int bn = blockIdx.x * BN;
    const int tid = threadIdx.x;

    // global->shared load mapping: 256 threads x float4 = 1024 floats (128x8 tile)
    const int lrow = tid >> 1;          // 0..127
    const int lcol = (tid & 1) * 4;     // 0 or 4

    // thread tile position: 16x16 grid of 8x8 microtiles
    const int tx = tid & 15;            // 0..15
    const int ty = tid >> 4;            // 0..15

    const float* xptr = X    + (size_t)(bm + lrow) * IN_DIM + lcol;
    const float* wptr = g_W  + (size_t)(bn + lrow) * IN_DIM + lcol;

    float acc[TM][TN];
#pragma unroll
    for (int i = 0; i < TM; i++)
#pragma unroll
        for (int j = 0; j < TN; j++) acc[i][j] = 0.f;

    for (int k0 = 0; k0 < IN_DIM; k0 += BK) {
        float4 xa = *(const float4*)(xptr + k0);
        float4 wa = *(const float4*)(wptr + k0);
        As[lcol + 0][lrow] = xa.x;
        As[lcol + 1][lrow] = xa.y;
        As[lcol + 2][lrow] = xa.z;
        As[lcol + 3][lrow] = xa.w;
        Bs[lcol + 0][lrow] = wa.x;
        Bs[lcol + 1][lrow] = wa.y;
        Bs[lcol + 2][lrow] = wa.z;
        Bs[lcol + 3][lrow] = wa.w;
        __syncthreads();

#pragma unroll
        for (int k = 0; k < BK; k++) {
            float af[TM], bf[TN];
            // vector loads from shared
            float4 a0 = *(const float4*)&As[k][ty * TM];
            float4 a1 = *(const float4*)&As[k][ty * TM + 4];
            float4 b0 = *(const float4*)&Bs[k][tx * TN];
            float4 b1 = *(const float4*)&Bs[k][tx * TN + 4];
            af[0]=a0.x; af[1]=a0.y; af[2]=a0.z; af[3]=a0.w;
            af[4]=a1.x; af[5]=a1.y; af[6]=a1.z; af[7]=a1.w;
            bf[0]=b0.x; bf[1]=b0.y; bf[2]=b0.z; bf[3]=b0.w;
            bf[4]=b1.x; bf[5]=b1.y; bf[6]=b1.z; bf[7]=b1.w;
#pragma unroll
            for (int i = 0; i < TM; i++)
#pragma unroll
                for (int j = 0; j < TN; j++)
                    acc[i][j] = fmaf(af[i], bf[j], acc[i][j]);
        }
        __syncthreads();
    }

    // epilogue: add bias, store float4
    const int ncol = bn + tx * TN;
    float bcol[TN];
#pragma unroll
    for (int j = 0; j < TN; j++) bcol[j] = bias[ncol + j];

#pragma unroll
    for (int i = 0; i < TM; i++) {
        int m = bm + ty * TM + i;
        float* yr = Y + (size_t)m * OUT_DIM + ncol;
        float4 v0, v1;
        v0.x = acc[i][0] + bcol[0];
        v0.y = acc[i][1] + bcol[1];
        v0.z = acc[i][2] + bcol[2];
        v0.w = acc[i][3] + bcol[3];
        v1.x = acc[i][4] + bcol[4];
        v1.y = acc[i][5] + bcol[5];
        v1.z = acc[i][6] + bcol[6];
        v1.w = acc[i][7] + bcol[7];
        *(float4*)(yr)     = v0;
        *(float4*)(yr + 4) = v1;
    }
}

// ---------------------------------------------------------------------------
extern "C" void kernel_launch(void* const* d_in, const int* in_sizes, int n_in,
                              void* d_out, int out_size) {
    const float* x       = (const float*)d_in[0];
    const int*   indices = (const int*)  d_in[1];
    const float* lut     = (const float*)d_in[2];
    const float* A       = (const float*)d_in[3];
    const float* Bm      = (const float*)d_in[4];
    const float* mag     = (const float*)d_in[5];
    const float* bias    = (const float*)d_in[6];
    float* y = (float*)d_out;

    const int M = out_size / OUT_DIM;   // B*S = 8192

    stats_kernel<<<1, 128>>>(A, Bm, mag);

    int n_w_threads = (OUT_DIM * IN_DIM) / 4;
    build_w_kernel<<<n_w_threads / 256, 256>>>(A, Bm, indices, lut);

    dim3 grid(OUT_DIM / BN, M / BM);
    sgemm_kernel<<<grid, 256>>>(x, bias, y);
}

// round 3
// speedup vs baseline: 3.5611x; 3.5611x over previous
#include <cuda_runtime.h>
#include <math.h>
#include <stdint.h>

#define OUT_DIM 2048
#define IN_DIM  2048
#define RANK    4
#define NORM_EPS 1e-6f
#define MAG_EPS  1e-6f

// GEMM tiling
#define BM 128
#define BN 256
#define BK 32
#define KT (IN_DIM / BK)          // 64 k-tiles
#define PAD 36                    // floats per smem row (144B, 16B-aligned, conflict-free)
#define STAGES 4
#define A_SM_BYTES (BM * PAD * 4)            // 18432
#define STAGE_BYTES ((BM + BN) * PAD * 4)    // 55296
#define SMEM_TOTAL (STAGES * STAGE_BYTES)    // 221184

// scratch: effective weight (tf32-rounded fp32 bit patterns), row-major [out][in]
__device__ float g_W[OUT_DIM * IN_DIM];
// stats: [0..3]=normA, [4..7]=normB, [8..11]=g
__device__ float g_stats[3 * RANK];

// ---------------------------------------------------------------------------
// PTX helpers (arch-portable: sm_80+ features only)
// ---------------------------------------------------------------------------
__device__ __forceinline__ uint32_t smem_u32(const void* p) {
    uint32_t a;
    asm("{ .reg .u64 t; cvta.to.shared.u64 t, %1; cvt.u32.u64 %0, t; }" : "=r"(a) : "l"(p));
    return a;
}
#define CP_ASYNC16(dst, src) \
    asm volatile("cp.async.cg.shared.global [%0], [%1], 16;" :: "r"(dst), "l"(src))
#define CP_COMMIT() asm volatile("cp.async.commit_group;" ::: "memory")
#define CP_WAIT(n)  asm volatile("cp.async.wait_group %0;" :: "n"(n) : "memory")
#define LDSM4(r0, r1, r2, r3, addr) \
    asm volatile("ldmatrix.sync.aligned.m8n8.x4.shared.b16 {%0,%1,%2,%3}, [%4];" \
        : "=r"(r0), "=r"(r1), "=r"(r2), "=r"(r3) : "r"(addr))

__device__ __forceinline__ void mma_tf32(float* d, const uint32_t* a, uint32_t b0, uint32_t b1) {
    asm volatile("mma.sync.aligned.m16n8k8.row.col.f32.tf32.tf32.f32 "
        "{%0,%1,%2,%3}, {%4,%5,%6,%7}, {%8,%9}, {%0,%1,%2,%3};"
        : "+f"(d[0]), "+f"(d[1]), "+f"(d[2]), "+f"(d[3])
        : "r"(a[0]), "r"(a[1]), "r"(a[2]), "r"(a[3]), "r"(b0), "r"(b1));
}

// ---------------------------------------------------------------------------
// Kernel 1: per-rank norms + softplus magnitude
// ---------------------------------------------------------------------------
__global__ void stats_kernel(const float* __restrict__ A,
                             const float* __restrict__ Bm,
                             const float* __restrict__ mag) {
    int r = threadIdx.x >> 5, lane = threadIdx.x & 31;
    float sa = 0.f, sb = 0.f;
    for (int o = lane; o < OUT_DIM; o += 32) { float v = A[o * RANK + r]; sa += v * v; }
    for (int i = lane; i < IN_DIM; i += 32)  { float v = Bm[r * IN_DIM + i]; sb += v * v; }
#pragma unroll
    for (int off = 16; off; off >>= 1) {
        sa += __shfl_xor_sync(0xffffffffu, sa, off);
        sb += __shfl_xor_sync(0xffffffffu, sb, off);
    }
    if (lane == 0) {
        g_stats[r]        = fmaxf(sqrtf(sa), NORM_EPS);
        g_stats[RANK + r] = fmaxf(sqrtf(sb), NORM_EPS);
        float m = mag[r];
        float sp = (m > 15.f) ? m : log1pf(expf(m));
        g_stats[2 * RANK + r] = sp + MAG_EPS;
    }
}

// ---------------------------------------------------------------------------
// Kernel 2: materialize W[o][i] = lut[idx]*sum_r coef[o][r]*|B[r][i]|, tf32-RNA
// ---------------------------------------------------------------------------
__global__ void build_w_kernel(const float* __restrict__ A,
                               const float* __restrict__ Bm,
                               const int*   __restrict__ idx,
                               const float* __restrict__ lut) {
    int t = blockIdx.x * blockDim.x + threadIdx.x;
    int per_row = IN_DIM / 4;
    int o  = t / per_row;
    int i4 = (t - o * per_row) * 4;

    float coef[RANK];
#pragma unroll
    for (int r = 0; r < RANK; r++)
        coef[r] = fabsf(A[o * RANK + r]) * g_stats[2 * RANK + r]
                  / (g_stats[r] * g_stats[RANK + r]);

    float s[4] = {0.f, 0.f, 0.f, 0.f};
#pragma unroll
    for (int r = 0; r < RANK; r++) {
        float4 bv = *(const float4*)(Bm + r * IN_DIM + i4);
        s[0] += coef[r] * fabsf(bv.x);
        s[1] += coef[r] * fabsf(bv.y);
        s[2] += coef[r] * fabsf(bv.z);
        s[3] += coef[r] * fabsf(bv.w);
    }
    int4 iv = *(const int4*)(idx + o * IN_DIM + i4);
    float w0 = lut[iv.x] * s[0], w1 = lut[iv.y] * s[1];
    float w2 = lut[iv.z] * s[2], w3 = lut[iv.w] * s[3];
    uint32_t u0, u1, u2, u3;
    asm("cvt.rna.tf32.f32 %0, %1;" : "=r"(u0) : "f"(w0));
    asm("cvt.rna.tf32.f32 %0, %1;" : "=r"(u1) : "f"(w1));
    asm("cvt.rna.tf32.f32 %0, %1;" : "=r"(u2) : "f"(w2));
    asm("cvt.rna.tf32.f32 %0, %1;" : "=r"(u3) : "f"(w3));
    float4 w;
    w.x = __uint_as_float(u0); w.y = __uint_as_float(u1);
    w.z = __uint_as_float(u2); w.w = __uint_as_float(u3);
    *(float4*)(g_W + o * IN_DIM + i4) = w;
}

// ---------------------------------------------------------------------------
// Kernel 3: tf32 mma.sync GEMM, 128x256 CTA tile, 4-stage cp.async pipeline.
// Y[m][n] = sum_k X[m][k]*W[n][k] + bias[n]
// ---------------------------------------------------------------------------
__global__ __launch_bounds__(256, 1)
void gemm_mma(const float* __restrict__ X,
              const float* __restrict__ bias,
              float* __restrict__ Y) {
    extern __shared__ char smem[];
    const uint32_t sb = smem_u32(smem);
    const int tid = threadIdx.x, lane = tid & 31, wid = tid >> 5;
    const int wm = wid & 1, wn = wid >> 1;       // 2x4 warp grid, 64x64 warp tile
    const int bm = blockIdx.y * BM, bn = blockIdx.x * BN;

    // ldmatrix per-thread base offsets (x4: lane -> matrix lane>>3, row lane&7)
    const int mat = lane >> 3, rowin = lane & 7;
    // A submatrix order: {(m0..7,k0..3),(m8..15,k0..3),(m0..7,k4..7),(m8..15,k4..7)}
    const uint32_t a_base = ((uint32_t)(wm * 64 + (mat & 1) * 8 + rowin) * PAD + (mat >> 1) * 4) * 4;
    // B x4 covers two n8-tiles: {(n0..7,k0..3),(n0..7,k4..7),(n8..15,k0..3),(n8..15,k4..7)}
    const uint32_t b_base = ((uint32_t)(wn * 64 + (mat >> 1) * 8 + rowin) * PAD + (mat & 1) * 4) * 4;

    const float* Xb = X   + (size_t)bm * IN_DIM;
    const float* Wb = g_W + (size_t)bn * IN_DIM;

    float acc[4][8][4];
#pragma unroll
    for (int i = 0; i < 4; i++)
#pragma unroll
        for (int j = 0; j < 8; j++)
#pragma unroll
            for (int k = 0; k < 4; k++) acc[i][j][k] = 0.f;

    // ---- async stage loader: 16B chunks, A=1024 chunks, B=2048 chunks ----
    auto load_stage = [&](int s, int kt) {
        const uint32_t abase = sb + s * STAGE_BYTES;
        const uint32_t bbase = abase + A_SM_BYTES;
        const int kc = kt * BK;
#pragma unroll
        for (int i = 0; i < 4; i++) {
            int id = tid + i * 256;
            int r = id >> 3, c = (id & 7) * 4;
            CP_ASYNC16(abase + ((uint32_t)r * PAD + c) * 4,
                       Xb + (size_t)r * IN_DIM + kc + c);
        }
#pragma unroll
        for (int i = 0; i < 8; i++) {
            int id = tid + i * 256;
            int r = id >> 3, c = (id & 7) * 4;
            CP_ASYNC16(bbase + ((uint32_t)r * PAD + c) * 4,
                       Wb + (size_t)r * IN_DIM + kc + c);
        }
    };

    auto compute_stage = [&](int s) {
        const uint32_t abase = sb + s * STAGE_BYTES + a_base;
        const uint32_t bbase = sb + s * STAGE_BYTES + A_SM_BYTES + b_base;
#pragma unroll
        for (int ks = 0; ks < BK / 8; ks++) {
            uint32_t af[4][4], bf[4][4];
#pragma unroll
            for (int mt = 0; mt < 4; mt++)
                LDSM4(af[mt][0], af[mt][1], af[mt][2], af[mt][3],
                      abase + (uint32_t)mt * 16 * PAD * 4 + ks * 32);
#pragma unroll
            for (int j = 0; j < 4; j++)
                LDSM4(bf[j][0], bf[j][1], bf[j][2], bf[j][3],
                      bbase + (uint32_t)j * 16 * PAD * 4 + ks * 32);
#pragma unroll
            for (int mt = 0; mt < 4; mt++)
#pragma unroll
                for (int nt = 0; nt < 8; nt++)
                    mma_tf32(acc[mt][nt], af[mt],
                             bf[nt >> 1][(nt & 1) * 2], bf[nt >> 1][(nt & 1) * 2 + 1]);
        }
    };

    // ---- pipeline ----
#pragma unroll
    for (int s = 0; s < STAGES - 1; s++) { load_stage(s, s); CP_COMMIT(); }

    for (int kt = 0; kt < KT; kt++) {
        CP_WAIT(2);
        __syncthreads();
        if (kt + STAGES - 1 < KT) load_stage((kt + STAGES - 1) & 3, kt + STAGES - 1);
        CP_COMMIT();
        compute_stage(kt & 3);
    }

    // ---- epilogue: c0/c1 at (row=group, col=2*tid), c2/c3 at row+8 ----
    const int group = lane >> 2, tidg = lane & 3;
#pragma unroll
    for (int nt = 0; nt < 8; nt++) {
        int col = bn + wn * 64 + nt * 8 + tidg * 2;
        float b0 = bias[col], b1 = bias[col + 1];
#pragma unroll
        for (int mt = 0; mt < 4; mt++) {
            int r0 = bm + wm * 64 + mt * 16 + group;
            float2 v0, v1;
            v0.x = acc[mt][nt][0] + b0; v0.y = acc[mt][nt][1] + b1;
            v1.x = acc[mt][nt][2] + b0; v1.y = acc[mt][nt][3] + b1;
            *(float2*)(Y + (size_t)r0 * OUT_DIM + col)       = v0;
            *(float2*)(Y + (size_t)(r0 + 8) * OUT_DIM + col) = v1;
        }
    }
}

// ---------------------------------------------------------------------------
extern "C" void kernel_launch(void* const* d_in, const int* in_sizes, int n_in,
                              void* d_out, int out_size) {
    const float* x       = (const float*)d_in[0];
    const int*   indices = (const int*)  d_in[1];
    const float* lut     = (const float*)d_in[2];
    const float* A       = (const float*)d_in[3];
    const float* Bm      = (const float*)d_in[4];
    const float* mag     = (const float*)d_in[5];
    const float* bias    = (const float*)d_in[6];
    float* y = (float*)d_out;
    const int M = out_size / OUT_DIM;   // 8192

    stats_kernel<<<1, 128>>>(A, Bm, mag);
    build_w_kernel<<<(OUT_DIM * IN_DIM / 4) / 256, 256>>>(A, Bm, indices, lut);

    static int configured = 0;
    if (!configured) {
        cudaFuncSetAttribute(gemm_mma, cudaFuncAttributeMaxDynamicSharedMemorySize, SMEM_TOTAL);
        configured = 1;
    }
    gemm_mma<<<dim3(OUT_DIM / BN, M / BM), 256, SMEM_TOTAL>>>(x, bias, y);
}